// round 9
// baseline (speedup 1.0000x reference)
#include <cuda_runtime.h>
#include <math.h>
#include <stdint.h>

// ---------------- scratch (static device globals; no allocation) ----------------
__device__ float g_h1p[5 * 512 * 1024];     // gemm1 split-K partials
__device__ float g_h1[512 * 1024];
__device__ float g_h2p[8 * 512 * 128];
__device__ float g_h2[512 * 128];
__device__ float g_hidden[512 * 4096];      // [b][o*64+d]
__device__ float g_cfs[64 * 64 * 32];       // [x][y][h]
__device__ float g_csum[64 * 32];
__device__ float g_att[64 * 2048];          // [o][i*32+g]
__device__ float g_att2[64 * 2048];         // [o][j]
__device__ float g_Cpart[16 * 64 * 2112];
__device__ float g_C[64 * 2112];            // [o][e]
__device__ float g_GT[64 * 2112];           // [d][e] = G[e][d]

typedef unsigned long long ull;

__device__ __forceinline__ ull pack2(float x, float y) {
    ull r; asm("mov.b64 %0,{%1,%2};" : "=l"(r) : "f"(x), "f"(y)); return r;
}
__device__ __forceinline__ void ffma2(ull& d, ull a, ull b) {
    asm("fma.rn.f32x2 %0,%1,%2,%0;" : "+l"(d) : "l"(a), "l"(b));
}
__device__ __forceinline__ float2 unpack2(ull v) {
    float2 r; asm("mov.b64 {%0,%1},%2;" : "=f"(r.x), "=f"(r.y) : "l"(v)); return r;
}
__device__ __forceinline__ float eluf(float x) { return x > 0.f ? x : expm1f(x); }
__device__ __forceinline__ float rcpf(float x) {
    float r; asm("rcp.approx.f32 %0,%1;" : "=f"(r) : "f"(x)); return r;
}
__device__ __forceinline__ void cpasync16(uint32_t s, const void* g) {
    asm volatile("cp.async.ca.shared.global [%0], [%1], 16;" :: "r"(s), "l"(g));
}
__device__ __forceinline__ void cpcommit() { asm volatile("cp.async.commit_group;"); }
__device__ __forceinline__ void cpwait0() { asm volatile("cp.async.wait_group 0;"); }

// ---------------- device sgemm (NT, double-buffered, f32x2) ---------------------
// C = act(A[M,K]*B[N,K]^T + bias); 64x64 tile, 256 thr, 4x4/thread; dsm: 4352 floats
__device__ __forceinline__ void dev_sgemm(
    float* dsm, int bx, int by, int bz, int nz,
    const float* __restrict__ A, const float* __restrict__ B,
    const float* __restrict__ bias, float* __restrict__ C,
    int N, int K, int lda, int ldb, int koffB, int relu, int zstride) {
    float* As = dsm;            // 2 buffers x 1088
    float* Bs = dsm + 2176;
    int t = threadIdx.x;
    int tx = t & 15, ty = t >> 4;
    int row0 = by * 64, col0 = bx * 64;
    int kPer = K / nz;
    int k0 = bz * kPer;
    const float* Ap = A + (size_t)(row0 + ty) * lda + k0 + tx;
    const float* Bp = B + (size_t)(col0 + ty) * ldb + koffB + k0 + tx;
    float ra[4], rb[4];
#pragma unroll
    for (int q = 0; q < 4; q++) {
        ra[q] = Ap[(size_t)q * 16 * lda];
        rb[q] = Bp[(size_t)q * 16 * ldb];
    }
#pragma unroll
    for (int q = 0; q < 4; q++) {
        As[tx * 68 + ty + q * 16] = ra[q];
        Bs[tx * 68 + ty + q * 16] = rb[q];
    }
    __syncthreads();
    ull acc[4][2] = {};
    int buf = 0;
    for (int kb = 16; kb <= kPer; kb += 16) {
        if (kb < kPer) {
#pragma unroll
            for (int q = 0; q < 4; q++) {
                ra[q] = Ap[kb + (size_t)q * 16 * lda];
                rb[q] = Bp[kb + (size_t)q * 16 * ldb];
            }
        }
#pragma unroll
        for (int kk = 0; kk < 16; kk++) {
            float4 av = *(const float4*)&As[buf * 1088 + kk * 68 + ty * 4];
            ulonglong2 bp = *(const ulonglong2*)&Bs[buf * 1088 + kk * 68 + tx * 4];
            ull a0 = pack2(av.x, av.x), a1 = pack2(av.y, av.y);
            ull a2 = pack2(av.z, av.z), a3 = pack2(av.w, av.w);
            ffma2(acc[0][0], a0, bp.x); ffma2(acc[0][1], a0, bp.y);
            ffma2(acc[1][0], a1, bp.x); ffma2(acc[1][1], a1, bp.y);
            ffma2(acc[2][0], a2, bp.x); ffma2(acc[2][1], a2, bp.y);
            ffma2(acc[3][0], a3, bp.x); ffma2(acc[3][1], a3, bp.y);
        }
        if (kb < kPer) {
            int nb = buf ^ 1;
#pragma unroll
            for (int q = 0; q < 4; q++) {
                As[nb * 1088 + tx * 68 + ty + q * 16] = ra[q];
                Bs[nb * 1088 + tx * 68 + ty + q * 16] = rb[q];
            }
            __syncthreads();
            buf = nb;
        }
    }
#pragma unroll
    for (int i = 0; i < 4; i++) {
        int m = row0 + ty * 4 + i;
#pragma unroll
        for (int j = 0; j < 2; j++) {
            float2 v = unpack2(acc[i][j]);
            int n = col0 + tx * 4 + 2 * j;
            if (bias) { v.x += bias[n]; v.y += bias[n + 1]; }
            if (relu) { v.x = fmaxf(v.x, 0.f); v.y = fmaxf(v.y, 0.f); }
            float* dst = C + (size_t)zstride * bz + (size_t)m * N + n;
            dst[0] = v.x;
            dst[1] = v.y;
        }
    }
}

// ---------------- device cfcfs: 16 pairs per block ------------------------------
__device__ __forceinline__ void dev_cfcfs(
    float* cawT, int pb, const float* __restrict__ cm,
    const float* __restrict__ cw, const float* __restrict__ cb,
    const float* __restrict__ caw) {
    __shared__ float sc[256], red[8], sp[256], scm[128];
    int t = threadIdx.x;
    int f = t >> 5, g = t & 31;
#pragma unroll
    for (int q = 0; q < 32; q++) {
        int l = t + q * 256;
        int ff = l >> 10, r = l & 1023, gg = r >> 5, h = r & 31;
        cawT[ff * 1056 + h * 33 + gg] = caw[l];
    }
    if (t < 128) scm[t] = cm[pb * 128 + t];
    float cwv = cw[t], cbv = cb[t];
    __syncthreads();
    for (int p = 0; p < 16; p++) {
        float m = scm[p * 8 + f];
        float v = eluf(fmaf(m, cwv, cbv));
        sc[t] = v;
        float r = expf(eluf(v));
#pragma unroll
        for (int off = 16; off; off >>= 1) r += __shfl_xor_sync(0xffffffffu, r, off);
        if (g == 0) red[f] = r;
        __syncthreads();
        float sden = 0.f;
#pragma unroll
        for (int q = 0; q < 8; q++) sden += red[q];
        float lin = 0.f;
#pragma unroll
        for (int h = 0; h < 32; h++) lin = fmaf(sc[f * 32 + h], cawT[f * 1056 + h * 33 + g], lin);
        float E = expf(eluf(v));
        sp[t] = eluf(E * lin / sden);
        __syncthreads();
        if (t < 32) {
            float sum = 0.f;
#pragma unroll
            for (int ff2 = 0; ff2 < 8; ff2++) sum += sp[ff2 * 32 + t];
            g_cfs[(pb * 16 + p) * 32 + t] = eluf(sum * 0.125f);
        }
        __syncthreads();
    }
}

// ---------------- fat1: gemm1 split-K=5 | cfcfs | GT transpose ------------------
__global__ __launch_bounds__(256) void fat1(
    const float* __restrict__ x, const float* __restrict__ fiW,
    const float* __restrict__ cm, const float* __restrict__ cw,
    const float* __restrict__ cb, const float* __restrict__ caw,
    const float* __restrict__ G) {
    extern __shared__ __align__(16) float dsm[];
    int b = blockIdx.x;
    if (b < 640) {
        int bx = b % 16, by = (b / 16) % 8, bz = b / 128;
        dev_sgemm(dsm, bx, by, bz, 5, x, fiW, nullptr, g_h1p,
                  1024, 2000, 2000, 2000, 0, 0, 524288);
    } else if (b < 896) {
        dev_cfcfs(dsm, b - 640, cm, cw, cb, caw);
    } else {
        int i = (b - 896) * 256 + threadIdx.x;   // 135168
        int d = i / 2112, e = i % 2112;
        g_GT[i] = G[(size_t)e * 2112 + d];
    }
}

// ---------------- fat2: redH1 (+bias+relu) | csum -------------------------------
__global__ __launch_bounds__(256) void fat2(const float* __restrict__ fib) {
    int b = blockIdx.x;
    int t = threadIdx.x;
    if (b < 2048) {
        int idx = b * 256 + t;                   // 524288
        float s = 0.f;
#pragma unroll
        for (int z = 0; z < 5; z++) s += g_h1p[z * 524288 + idx];
        g_h1[idx] = fmaxf(s + fib[idx & 1023], 0.f);
    } else {
        int xq = b - 2048;                       // 64
        int ys = t >> 5, h = t & 31;
        float s = 0.f;
        for (int y = ys; y < 64; y += 8) s += expf(eluf(g_cfs[(xq * 64 + y) * 32 + h]));
        __shared__ float r[256];
        r[t] = s;
        __syncthreads();
        if (t < 32) {
            float a = 0.f;
#pragma unroll
            for (int q = 0; q < 8; q++) a += r[q * 32 + t];
            g_csum[xq * 32 + t] = a;
        }
    }
}

// ---------------- fat3: gemm2 split-K=8 | att ------------------------------------
__global__ __launch_bounds__(256) void fat3(const float* __restrict__ f1W,
                                            const float* __restrict__ oaw) {
    extern __shared__ __align__(16) float dsm[];
    int b = blockIdx.x;
    int t = threadIdx.x;
    if (b < 128) {
        int bx = b % 2, by = (b / 2) % 8, bz = b / 16;
        dev_sgemm(dsm, bx, by, bz, 8, g_h1, f1W, nullptr, g_h2p,
                  128, 1024, 1024, 1024, 0, 0, 65536);
    } else {
        int bq = b - 128;                        // 256
        int i = bq >> 2, og = bq & 3;
        int osub = t >> 5, g = t & 31;
        __shared__ float sw[32 * 33];
        __shared__ float scf[16 * 32];
#pragma unroll
        for (int q = 0; q < 4; q++) {
            int l = t + q * 256;
            int gg = l >> 5, h = l & 31;
            sw[h * 33 + gg] = oaw[i * 1024 + l];
        }
#pragma unroll
        for (int q = 0; q < 2; q++) {
            int l = t + q * 256;
            int op = l >> 5, h = l & 31;
            scf[l] = g_cfs[((og * 16 + op) * 64 + i) * 32 + h];
        }
        __syncthreads();
#pragma unroll
        for (int q = 0; q < 2; q++) {
            int op = osub * 2 + q;
            int o = og * 16 + op;
            float lin = 0.f;
#pragma unroll
            for (int h = 0; h < 32; h++) lin = fmaf(scf[op * 32 + h], sw[h * 33 + g], lin);
            float E = expf(eluf(scf[op * 32 + g]));
            g_att[o * 2048 + i * 32 + g] = E / g_csum[o * 32 + g] * lin;
        }
    }
}

// ---------------- fat4: att2 | redH (+bias+relu) ---------------------------------
__global__ __launch_bounds__(256) void fat4(const float* __restrict__ wnt,
                                            const float* __restrict__ f1b) {
    int b = blockIdx.x;
    int t = threadIdx.x;
    if (b < 512) {
        int idx = b * 256 + t;                   // 131072
        int o = idx >> 11, j = idx & 2047;
        float acc = 0.f;
#pragma unroll 8
        for (int p = 0; p < 64; p++) acc += wnt[o * 64 + p] * g_att[p * 2048 + j];
        g_att2[idx] = acc;
    } else {
        int idx = (b - 512) * 256 + t;           // 65536
        float s = 0.f;
#pragma unroll
        for (int z = 0; z < 8; z++) s += g_h2p[z * 65536 + idx];
        g_h2[idx] = fmaxf(s + f1b[idx & 127], 0.f);
    }
}

// ---------------- fat5: C gemm split-K=16 | gemm3 --------------------------------
__global__ __launch_bounds__(256) void fat5(const float* __restrict__ gW,
                                            const float* __restrict__ o1W,
                                            const float* __restrict__ o1b) {
    extern __shared__ __align__(16) float dsm[];
    int b = blockIdx.x;
    if (b < 528) {
        int bx = b % 33, bz = b / 33;
        dev_sgemm(dsm, bx, 0, bz, 16, g_att2, gW, nullptr, g_Cpart,
                  2112, 2048, 2048, 2112, 64, 0, 135168);
    } else {
        int r = b - 528;                         // 512
        int bx = r % 64, by = r / 64;
        dev_sgemm(dsm, bx, by, 0, 1, g_h2, o1W, o1b, g_hidden,
                  4096, 128, 128, 128, 0, 1, 0);
    }
}

// deterministic split-K reduce for C
__global__ void k_redC() {
    int i = blockIdx.x * 256 + threadIdx.x;     // 135168
    float s = 0.f;
#pragma unroll
    for (int z = 0; z < 16; z++) s += g_Cpart[z * 135168 + i];
    g_C[i] = s;
}

// ---------------- fused final: U + y GEMM + sigmoid + weighted reduce ----------
__global__ __launch_bounds__(256, 2) void k_final(
    const float* __restrict__ Wnt, const float* __restrict__ wout,
    const float* __restrict__ outb, const float* __restrict__ pa,
    float* __restrict__ out) {
    extern __shared__ __align__(16) float smem[];
    float* sUT = smem;               // 8448
    float* sA0 = sUT + 8448;         // 4352
    float* sA1 = sA0 + 4352;         // 4352
    float* sB  = sA1 + 4352;         // 2112
    float* sC0 = sB + 2112;          // 4352
    float* sC1 = sC0 + 4352;         // 4352
    const float* GT = g_GT;
    const float* Cg = g_C;
    int t = threadIdx.x;
    int tx = t & 15, ty = t >> 4;
    int bpair = blockIdx.x;
    uint32_t sA0u = (uint32_t)__cvta_generic_to_shared(sA0);
    uint32_t sA1u = (uint32_t)__cvta_generic_to_shared(sA1);
    uint32_t sC0u = (uint32_t)__cvta_generic_to_shared(sC0);
    uint32_t sC1u = (uint32_t)__cvta_generic_to_shared(sC1);

    // prefetch G tile 0 -> sA1 (overlaps the whole U phase)
#pragma unroll
    for (int q = 0; q < 4; q++) {
        int u = t + q * 256;
        int d = u >> 4, e4 = u & 15;
        cpasync16(sA1u + (d * 68 + e4 * 4) * 4, GT + (size_t)d * 2112 + e4 * 4);
    }
    cpcommit();

    // stage Wnt transposed: sA0[p][o]
#pragma unroll
    for (int q = 0; q < 16; q++) {
        int l = t + q * 256;
        int o = l >> 6, p = l & 63;
        sA0[p * 68 + o] = Wnt[l];
    }

    for (int bb = 0; bb < 2; bb++) {
        const float4* hid = (const float4*)(g_hidden + (size_t)(2 * bpair + bb) * 4096);
#pragma unroll
        for (int q = 0; q < 4; q++) {
            int l4 = t + q * 256;
            int p = l4 >> 4, d = (l4 & 15) * 4;
            *(float4*)&sC0[p * 68 + d] = hid[l4];
        }
        __syncthreads();
        ull uacc[4][2] = {};
#pragma unroll 8
        for (int p = 0; p < 64; p++) {
            float4 av = *(const float4*)&sA0[p * 68 + ty * 4];
            ulonglong2 bp2 = *(const ulonglong2*)&sC0[p * 68 + tx * 4];
            ull a0 = pack2(av.x, av.x), a1 = pack2(av.y, av.y);
            ull a2 = pack2(av.z, av.z), a3 = pack2(av.w, av.w);
            ffma2(uacc[0][0], a0, bp2.x); ffma2(uacc[0][1], a0, bp2.y);
            ffma2(uacc[1][0], a1, bp2.x); ffma2(uacc[1][1], a1, bp2.y);
            ffma2(uacc[2][0], a2, bp2.x); ffma2(uacc[2][1], a2, bp2.y);
            ffma2(uacc[3][0], a3, bp2.x); ffma2(uacc[3][1], a3, bp2.y);
        }
#pragma unroll
        for (int i = 0; i < 4; i++) {
            int o = ty * 4 + i;
#pragma unroll
            for (int j = 0; j < 2; j++) {
                float2 v = unpack2(uacc[i][j]);
                int d = tx * 4 + 2 * j;
                sUT[d * 132 + bb * 64 + o] = v.x;
                sUT[(d + 1) * 132 + bb * 64 + o] = v.y;
            }
        }
        __syncthreads();
    }

    // sC0 free now: prefetch C tile 0
#pragma unroll
    for (int q = 0; q < 4; q++) {
        int u = t + q * 256;
        int o = u >> 4, e4 = u & 15;
        cpasync16(sC0u + (o * 68 + e4 * 4) * 4, Cg + (size_t)o * 2112 + e4 * 4);
    }
    cpcommit();

    // stage wout
    for (int l = t; l < 2112; l += 256) sB[l] = wout[l];

    float zacc[8] = {0.f, 0.f, 0.f, 0.f, 0.f, 0.f, 0.f, 0.f};
    int r0 = ty * 8, e0 = tx * 4;

    for (int et = 0; et < 33; et++) {
        cpwait0();
        __syncthreads();
        float* gbuf = (et & 1) ? sA0 : sA1;
        float* cbuf = (et & 1) ? sC1 : sC0;
        if (et < 32) {
            uint32_t gd = (et & 1) ? sA1u : sA0u;
            uint32_t cd = (et & 1) ? sC0u : sC1u;
            const float* gsrc = GT + (et + 1) * 64;
            const float* csrc = Cg + (et + 1) * 64;
#pragma unroll
            for (int q = 0; q < 4; q++) {
                int u = t + q * 256;
                int r = u >> 4, e4 = u & 15;
                cpasync16(gd + (r * 68 + e4 * 4) * 4, gsrc + (size_t)r * 2112 + e4 * 4);
                cpasync16(cd + (r * 68 + e4 * 4) * 4, csrc + (size_t)r * 2112 + e4 * 4);
            }
            cpcommit();
        }
        ull yacc[4][4] = {};
#pragma unroll 4
        for (int d = 0; d < 64; d++) {
            const float* put = &sUT[d * 132 + r0];
            ulonglong2 up0 = *(const ulonglong2*)(put);
            ulonglong2 up1 = *(const ulonglong2*)(put + 4);
            float4 gv = *(const float4*)&gbuf[d * 68 + e0];
            ull g0 = pack2(gv.x, gv.x), g1 = pack2(gv.y, gv.y);
            ull g2 = pack2(gv.z, gv.z), g3 = pack2(gv.w, gv.w);
            ffma2(yacc[0][0], up0.x, g0); ffma2(yacc[0][1], up0.x, g1);
            ffma2(yacc[0][2], up0.x, g2); ffma2(yacc[0][3], up0.x, g3);
            ffma2(yacc[1][0], up0.y, g0); ffma2(yacc[1][1], up0.y, g1);
            ffma2(yacc[1][2], up0.y, g2); ffma2(yacc[1][3], up0.y, g3);
            ffma2(yacc[2][0], up1.x, g0); ffma2(yacc[2][1], up1.x, g1);
            ffma2(yacc[2][2], up1.x, g2); ffma2(yacc[2][3], up1.x, g3);
            ffma2(yacc[3][0], up1.y, g0); ffma2(yacc[3][1], up1.y, g1);
            ffma2(yacc[3][2], up1.y, g2); ffma2(yacc[3][3], up1.y, g3);
        }
        float4 wv = *(const float4*)&sB[et * 64 + e0];
        float wj[4] = {wv.x, wv.y, wv.z, wv.w};
#pragma unroll
        for (int rp = 0; rp < 4; rp++) {
            int rA = r0 + 2 * rp;
            int oA = rA & 63, oB = (rA + 1) & 63;
            float4 cA = *(const float4*)&cbuf[oA * 68 + e0];
            float4 cB = *(const float4*)&cbuf[oB * 68 + e0];
            float cAj[4] = {cA.x, cA.y, cA.z, cA.w};
            float cBj[4] = {cB.x, cB.y, cB.z, cB.w};
#pragma unroll
            for (int j = 0; j < 4; j++) {
                float2 y = unpack2(yacc[rp][j]);
                float ya = y.x + cAj[j];
                float yb = y.y + cBj[j];
                zacc[2 * rp]     += wj[j] * rcpf(1.f + __expf(-ya));
                zacc[2 * rp + 1] += wj[j] * rcpf(1.f + __expf(-yb));
            }
        }
    }

    __syncthreads();
#pragma unroll
    for (int i = 0; i < 8; i++) sA0[(r0 + i) * 16 + tx] = zacc[i];
    __syncthreads();
    if (t < 128) {
        float z = 0.f;
#pragma unroll
        for (int q = 0; q < 16; q++) z += sA0[t * 16 + q];
        z += outb[0];
        float a = pa[0];
        out[bpair * 128 + t] = z >= 0.f ? z : a * z;
    }
}

// ---------------- launcher ----------------
extern "C" void kernel_launch(void* const* d_in, const int* in_sizes, int n_in,
                              void* d_out, int out_size) {
    const float* x   = (const float*)d_in[0];
    const float* fiW = (const float*)d_in[1];
    const float* fib = (const float*)d_in[2];
    const float* f1W = (const float*)d_in[3];
    const float* f1b = (const float*)d_in[4];
    const float* o1W = (const float*)d_in[5];
    const float* o1b = (const float*)d_in[6];
    const float* cnW = (const float*)d_in[7];
    const float* cnb = (const float*)d_in[8];
    const float* caW = (const float*)d_in[9];
    const float* oaW = (const float*)d_in[10];
    const float* ntW = (const float*)d_in[11];
    const float* gW  = (const float*)d_in[12];
    const float* omW = (const float*)d_in[13];
    const float* omb = (const float*)d_in[14];
    const float* pa  = (const float*)d_in[15];
    const float* cm  = (const float*)d_in[16];
    float* out = (float*)d_out;

    cudaFuncSetAttribute(k_final, cudaFuncAttributeMaxDynamicSharedMemorySize, 111872);

    // fat1: gemm1 split-K=5 (640) | cfcfs (256) | GT transpose (528)
    fat1<<<1424, 256, 33792>>>(x, fiW, cm, cnW, cnb, caW, gW);
    // fat2: redH1+bias+relu (2048) | csum (64)
    fat2<<<2112, 256>>>(fib);
    // fat3: gemm2 split-K=8 (128) | att (256)
    fat3<<<384, 256, 17408>>>(f1W, oaW);
    // fat4: att2 (512) | redH+bias+relu (256)
    fat4<<<768, 256>>>(ntW, f1b);
    // fat5: C gemm split-K=16 (528) | gemm3 (512)
    fat5<<<1040, 256, 17408>>>(gW, o1W, o1b);
    k_redC<<<528, 256>>>();
    k_final<<<256, 256, 111872>>>(ntW, omW, omb, pa, out);
}

// round 10
// speedup vs baseline: 1.0010x; 1.0010x over previous
#include <cuda_runtime.h>
#include <math.h>
#include <stdint.h>

// ---------------- scratch (static device globals; no allocation) ----------------
__device__ float g_h1p[5 * 512 * 1024];     // gemm1 split-K partials
__device__ float g_h1[512 * 1024];
__device__ float g_h2p[8 * 512 * 128];
__device__ float g_h2[512 * 128];
__device__ float g_hidden[512 * 4096];      // [b][o*64+d]
__device__ float g_cfs[64 * 64 * 32];       // [x][y][h]
__device__ float g_csum[64 * 32];
__device__ float g_att[64 * 2048];          // [o][i*32+g]
__device__ float g_att2[64 * 2048];         // [o][j]
__device__ float g_Cpart[16 * 64 * 2112];
__device__ float g_C[64 * 2112];            // [o][e]
__device__ float g_GT[64 * 2112];           // [d][e] = G[e][d]

typedef unsigned long long ull;

__device__ __forceinline__ ull pack2(float x, float y) {
    ull r; asm("mov.b64 %0,{%1,%2};" : "=l"(r) : "f"(x), "f"(y)); return r;
}
__device__ __forceinline__ void ffma2(ull& d, ull a, ull b) {
    asm("fma.rn.f32x2 %0,%1,%2,%0;" : "+l"(d) : "l"(a), "l"(b));
}
__device__ __forceinline__ float2 unpack2(ull v) {
    float2 r; asm("mov.b64 {%0,%1},%2;" : "=f"(r.x), "=f"(r.y) : "l"(v)); return r;
}
__device__ __forceinline__ float eluf(float x) { return x > 0.f ? x : expm1f(x); }
__device__ __forceinline__ float rcpf(float x) {
    float r; asm("rcp.approx.f32 %0,%1;" : "=f"(r) : "f"(x)); return r;
}
__device__ __forceinline__ void cpasync16(uint32_t s, const void* g) {
    asm volatile("cp.async.ca.shared.global [%0], [%1], 16;" :: "r"(s), "l"(g));
}
__device__ __forceinline__ void cpcommit() { asm volatile("cp.async.commit_group;"); }
__device__ __forceinline__ void cpwait0() { asm volatile("cp.async.wait_group 0;"); }

// ---------------- device sgemm (NT, double-buffered, f32x2) ---------------------
// C = act(A[M,K]*B[N,K]^T + bias); 64x64 tile, 256 thr, 4x4/thread; dsm: 4352 floats
__device__ __forceinline__ void dev_sgemm(
    float* dsm, int bx, int by, int bz, int nz,
    const float* __restrict__ A, const float* __restrict__ B,
    const float* __restrict__ bias, float* __restrict__ C,
    int N, int K, int lda, int ldb, int koffB, int relu, int zstride) {
    float* As = dsm;            // 2 buffers x 1088
    float* Bs = dsm + 2176;
    int t = threadIdx.x;
    int tx = t & 15, ty = t >> 4;
    int row0 = by * 64, col0 = bx * 64;
    int kPer = K / nz;
    int k0 = bz * kPer;
    const float* Ap = A + (size_t)(row0 + ty) * lda + k0 + tx;
    const float* Bp = B + (size_t)(col0 + ty) * ldb + koffB + k0 + tx;
    float ra[4], rb[4];
#pragma unroll
    for (int q = 0; q < 4; q++) {
        ra[q] = Ap[(size_t)q * 16 * lda];
        rb[q] = Bp[(size_t)q * 16 * ldb];
    }
#pragma unroll
    for (int q = 0; q < 4; q++) {
        As[tx * 68 + ty + q * 16] = ra[q];
        Bs[tx * 68 + ty + q * 16] = rb[q];
    }
    __syncthreads();
    ull acc[4][2] = {};
    int buf = 0;
    for (int kb = 16; kb <= kPer; kb += 16) {
        if (kb < kPer) {
#pragma unroll
            for (int q = 0; q < 4; q++) {
                ra[q] = Ap[kb + (size_t)q * 16 * lda];
                rb[q] = Bp[kb + (size_t)q * 16 * ldb];
            }
        }
#pragma unroll
        for (int kk = 0; kk < 16; kk++) {
            float4 av = *(const float4*)&As[buf * 1088 + kk * 68 + ty * 4];
            ulonglong2 bp = *(const ulonglong2*)&Bs[buf * 1088 + kk * 68 + tx * 4];
            ull a0 = pack2(av.x, av.x), a1 = pack2(av.y, av.y);
            ull a2 = pack2(av.z, av.z), a3 = pack2(av.w, av.w);
            ffma2(acc[0][0], a0, bp.x); ffma2(acc[0][1], a0, bp.y);
            ffma2(acc[1][0], a1, bp.x); ffma2(acc[1][1], a1, bp.y);
            ffma2(acc[2][0], a2, bp.x); ffma2(acc[2][1], a2, bp.y);
            ffma2(acc[3][0], a3, bp.x); ffma2(acc[3][1], a3, bp.y);
        }
        if (kb < kPer) {
            int nb = buf ^ 1;
#pragma unroll
            for (int q = 0; q < 4; q++) {
                As[nb * 1088 + tx * 68 + ty + q * 16] = ra[q];
                Bs[nb * 1088 + tx * 68 + ty + q * 16] = rb[q];
            }
            __syncthreads();
            buf = nb;
        }
    }
#pragma unroll
    for (int i = 0; i < 4; i++) {
        int m = row0 + ty * 4 + i;
#pragma unroll
        for (int j = 0; j < 2; j++) {
            float2 v = unpack2(acc[i][j]);
            int n = col0 + tx * 4 + 2 * j;
            if (bias) { v.x += bias[n]; v.y += bias[n + 1]; }
            if (relu) { v.x = fmaxf(v.x, 0.f); v.y = fmaxf(v.y, 0.f); }
            float* dst = C + (size_t)zstride * bz + (size_t)m * N + n;
            dst[0] = v.x;
            dst[1] = v.y;
        }
    }
}

// ---------------- device cfcfs: 16 pairs per block ------------------------------
__device__ __forceinline__ void dev_cfcfs(
    float* cawT, int pb, const float* __restrict__ cm,
    const float* __restrict__ cw, const float* __restrict__ cb,
    const float* __restrict__ caw) {
    __shared__ float sc[256], red[8], sp[256], scm[128];
    int t = threadIdx.x;
    int f = t >> 5, g = t & 31;
#pragma unroll
    for (int q = 0; q < 32; q++) {
        int l = t + q * 256;
        int ff = l >> 10, r = l & 1023, gg = r >> 5, h = r & 31;
        cawT[ff * 1056 + h * 33 + gg] = caw[l];
    }
    if (t < 128) scm[t] = cm[pb * 128 + t];
    float cwv = cw[t], cbv = cb[t];
    __syncthreads();
    for (int p = 0; p < 16; p++) {
        float m = scm[p * 8 + f];
        float v = eluf(fmaf(m, cwv, cbv));
        sc[t] = v;
        float r = expf(eluf(v));
#pragma unroll
        for (int off = 16; off; off >>= 1) r += __shfl_xor_sync(0xffffffffu, r, off);
        if (g == 0) red[f] = r;
        __syncthreads();
        float sden = 0.f;
#pragma unroll
        for (int q = 0; q < 8; q++) sden += red[q];
        float lin = 0.f;
#pragma unroll
        for (int h = 0; h < 32; h++) lin = fmaf(sc[f * 32 + h], cawT[f * 1056 + h * 33 + g], lin);
        float E = expf(eluf(v));
        sp[t] = eluf(E * lin / sden);
        __syncthreads();
        if (t < 32) {
            float sum = 0.f;
#pragma unroll
            for (int ff2 = 0; ff2 < 8; ff2++) sum += sp[ff2 * 32 + t];
            g_cfs[(pb * 16 + p) * 32 + t] = eluf(sum * 0.125f);
        }
        __syncthreads();
    }
}

// ---------------- fat1: gemm1 split-K=5 | cfcfs | GT transpose ------------------
__global__ __launch_bounds__(256) void fat1(
    const float* __restrict__ x, const float* __restrict__ fiW,
    const float* __restrict__ cm, const float* __restrict__ cw,
    const float* __restrict__ cb, const float* __restrict__ caw,
    const float* __restrict__ G) {
    extern __shared__ __align__(16) float dsm[];
    int b = blockIdx.x;
    if (b < 640) {
        int bx = b % 16, by = (b / 16) % 8, bz = b / 128;
        dev_sgemm(dsm, bx, by, bz, 5, x, fiW, nullptr, g_h1p,
                  1024, 2000, 2000, 2000, 0, 0, 524288);
    } else if (b < 896) {
        dev_cfcfs(dsm, b - 640, cm, cw, cb, caw);
    } else {
        int i = (b - 896) * 256 + threadIdx.x;   // 135168
        int d = i / 2112, e = i % 2112;
        g_GT[i] = G[(size_t)e * 2112 + d];
    }
}

// ---------------- fat2: redH1 (+bias+relu) | csum -------------------------------
__global__ __launch_bounds__(256) void fat2(const float* __restrict__ fib) {
    int b = blockIdx.x;
    int t = threadIdx.x;
    if (b < 2048) {
        int idx = b * 256 + t;                   // 524288
        float s = 0.f;
#pragma unroll
        for (int z = 0; z < 5; z++) s += g_h1p[z * 524288 + idx];
        g_h1[idx] = fmaxf(s + fib[idx & 1023], 0.f);
    } else {
        int xq = b - 2048;                       // 64
        int ys = t >> 5, h = t & 31;
        float s = 0.f;
        for (int y = ys; y < 64; y += 8) s += expf(eluf(g_cfs[(xq * 64 + y) * 32 + h]));
        __shared__ float r[256];
        r[t] = s;
        __syncthreads();
        if (t < 32) {
            float a = 0.f;
#pragma unroll
            for (int q = 0; q < 8; q++) a += r[q * 32 + t];
            g_csum[xq * 32 + t] = a;
        }
    }
}

// ---------------- fat3: gemm2 split-K=8 | att ------------------------------------
__global__ __launch_bounds__(256) void fat3(const float* __restrict__ f1W,
                                            const float* __restrict__ oaw) {
    extern __shared__ __align__(16) float dsm[];
    int b = blockIdx.x;
    int t = threadIdx.x;
    if (b < 128) {
        int bx = b % 2, by = (b / 2) % 8, bz = b / 16;
        dev_sgemm(dsm, bx, by, bz, 8, g_h1, f1W, nullptr, g_h2p,
                  128, 1024, 1024, 1024, 0, 0, 65536);
    } else {
        int bq = b - 128;                        // 256
        int i = bq >> 2, og = bq & 3;
        int osub = t >> 5, g = t & 31;
        __shared__ float sw[32 * 33];
        __shared__ float scf[16 * 32];
#pragma unroll
        for (int q = 0; q < 4; q++) {
            int l = t + q * 256;
            int gg = l >> 5, h = l & 31;
            sw[h * 33 + gg] = oaw[i * 1024 + l];
        }
#pragma unroll
        for (int q = 0; q < 2; q++) {
            int l = t + q * 256;
            int op = l >> 5, h = l & 31;
            scf[l] = g_cfs[((og * 16 + op) * 64 + i) * 32 + h];
        }
        __syncthreads();
#pragma unroll
        for (int q = 0; q < 2; q++) {
            int op = osub * 2 + q;
            int o = og * 16 + op;
            float lin = 0.f;
#pragma unroll
            for (int h = 0; h < 32; h++) lin = fmaf(scf[op * 32 + h], sw[h * 33 + g], lin);
            float E = expf(eluf(scf[op * 32 + g]));
            g_att[o * 2048 + i * 32 + g] = E / g_csum[o * 32 + g] * lin;
        }
    }
}

// ---------------- fat4: att2 | redH (+bias+relu) ---------------------------------
__global__ __launch_bounds__(256) void fat4(const float* __restrict__ wnt,
                                            const float* __restrict__ f1b) {
    int b = blockIdx.x;
    int t = threadIdx.x;
    if (b < 512) {
        int idx = b * 256 + t;                   // 131072
        int o = idx >> 11, j = idx & 2047;
        float acc = 0.f;
#pragma unroll 8
        for (int p = 0; p < 64; p++) acc += wnt[o * 64 + p] * g_att[p * 2048 + j];
        g_att2[idx] = acc;
    } else {
        int idx = (b - 512) * 256 + t;           // 65536
        float s = 0.f;
#pragma unroll
        for (int z = 0; z < 8; z++) s += g_h2p[z * 65536 + idx];
        g_h2[idx] = fmaxf(s + f1b[idx & 127], 0.f);
    }
}

// ---------------- fat5: C gemm split-K=16 | gemm3 --------------------------------
__global__ __launch_bounds__(256) void fat5(const float* __restrict__ gW,
                                            const float* __restrict__ o1W,
                                            const float* __restrict__ o1b) {
    extern __shared__ __align__(16) float dsm[];
    int b = blockIdx.x;
    if (b < 528) {
        int bx = b % 33, bz = b / 33;
        dev_sgemm(dsm, bx, 0, bz, 16, g_att2, gW, nullptr, g_Cpart,
                  2112, 2048, 2048, 2112, 64, 0, 135168);
    } else {
        int r = b - 528;                         // 512
        int bx = r % 64, by = r / 64;
        dev_sgemm(dsm, bx, by, 0, 1, g_h2, o1W, o1b, g_hidden,
                  4096, 128, 128, 128, 0, 1, 0);
    }
}

// deterministic split-K reduce for C
__global__ void k_redC() {
    int i = blockIdx.x * 256 + threadIdx.x;     // 135168
    float s = 0.f;
#pragma unroll
    for (int z = 0; z < 16; z++) s += g_Cpart[z * 135168 + i];
    g_C[i] = s;
}

// ---------------- fused final: U + y GEMM + sigmoid + weighted reduce ----------
__global__ __launch_bounds__(256, 2) void k_final(
    const float* __restrict__ Wnt, const float* __restrict__ wout,
    const float* __restrict__ outb, const float* __restrict__ pa,
    float* __restrict__ out) {
    extern __shared__ __align__(16) float smem[];
    float* sUT = smem;               // 8448
    float* sA0 = sUT + 8448;         // 4352
    float* sA1 = sA0 + 4352;         // 4352
    float* sB  = sA1 + 4352;         // 2112
    float* sC0 = sB + 2112;          // 4352
    float* sC1 = sC0 + 4352;         // 4352
    const float* GT = g_GT;
    const float* Cg = g_C;
    int t = threadIdx.x;
    int tx = t & 15, ty = t >> 4;
    int bpair = blockIdx.x;
    uint32_t sA0u = (uint32_t)__cvta_generic_to_shared(sA0);
    uint32_t sA1u = (uint32_t)__cvta_generic_to_shared(sA1);
    uint32_t sC0u = (uint32_t)__cvta_generic_to_shared(sC0);
    uint32_t sC1u = (uint32_t)__cvta_generic_to_shared(sC1);

    // prefetch G tile 0 -> sA1 (overlaps the whole U phase)
#pragma unroll
    for (int q = 0; q < 4; q++) {
        int u = t + q * 256;
        int d = u >> 4, e4 = u & 15;
        cpasync16(sA1u + (d * 68 + e4 * 4) * 4, GT + (size_t)d * 2112 + e4 * 4);
    }
    cpcommit();

    // stage Wnt transposed: sA0[p][o]
#pragma unroll
    for (int q = 0; q < 16; q++) {
        int l = t + q * 256;
        int o = l >> 6, p = l & 63;
        sA0[p * 68 + o] = Wnt[l];
    }

    for (int bb = 0; bb < 2; bb++) {
        const float4* hid = (const float4*)(g_hidden + (size_t)(2 * bpair + bb) * 4096);
#pragma unroll
        for (int q = 0; q < 4; q++) {
            int l4 = t + q * 256;
            int p = l4 >> 4, d = (l4 & 15) * 4;
            *(float4*)&sC0[p * 68 + d] = hid[l4];
        }
        __syncthreads();
        ull uacc[4][2] = {};
#pragma unroll 8
        for (int p = 0; p < 64; p++) {
            float4 av = *(const float4*)&sA0[p * 68 + ty * 4];
            ulonglong2 bp2 = *(const ulonglong2*)&sC0[p * 68 + tx * 4];
            ull a0 = pack2(av.x, av.x), a1 = pack2(av.y, av.y);
            ull a2 = pack2(av.z, av.z), a3 = pack2(av.w, av.w);
            ffma2(uacc[0][0], a0, bp2.x); ffma2(uacc[0][1], a0, bp2.y);
            ffma2(uacc[1][0], a1, bp2.x); ffma2(uacc[1][1], a1, bp2.y);
            ffma2(uacc[2][0], a2, bp2.x); ffma2(uacc[2][1], a2, bp2.y);
            ffma2(uacc[3][0], a3, bp2.x); ffma2(uacc[3][1], a3, bp2.y);
        }
#pragma unroll
        for (int i = 0; i < 4; i++) {
            int o = ty * 4 + i;
#pragma unroll
            for (int j = 0; j < 2; j++) {
                float2 v = unpack2(uacc[i][j]);
                int d = tx * 4 + 2 * j;
                sUT[d * 132 + bb * 64 + o] = v.x;
                sUT[(d + 1) * 132 + bb * 64 + o] = v.y;
            }
        }
        __syncthreads();
    }

    // sC0 free now: prefetch C tile 0
#pragma unroll
    for (int q = 0; q < 4; q++) {
        int u = t + q * 256;
        int o = u >> 4, e4 = u & 15;
        cpasync16(sC0u + (o * 68 + e4 * 4) * 4, Cg + (size_t)o * 2112 + e4 * 4);
    }
    cpcommit();

    // stage wout
    for (int l = t; l < 2112; l += 256) sB[l] = wout[l];

    float zacc[8] = {0.f, 0.f, 0.f, 0.f, 0.f, 0.f, 0.f, 0.f};
    int r0 = ty * 8, e0 = tx * 4;

    for (int et = 0; et < 33; et++) {
        cpwait0();
        __syncthreads();
        float* gbuf = (et & 1) ? sA0 : sA1;
        float* cbuf = (et & 1) ? sC1 : sC0;
        if (et < 32) {
            uint32_t gd = (et & 1) ? sA1u : sA0u;
            uint32_t cd = (et & 1) ? sC0u : sC1u;
            const float* gsrc = GT + (et + 1) * 64;
            const float* csrc = Cg + (et + 1) * 64;
#pragma unroll
            for (int q = 0; q < 4; q++) {
                int u = t + q * 256;
                int r = u >> 4, e4 = u & 15;
                cpasync16(gd + (r * 68 + e4 * 4) * 4, gsrc + (size_t)r * 2112 + e4 * 4);
                cpasync16(cd + (r * 68 + e4 * 4) * 4, csrc + (size_t)r * 2112 + e4 * 4);
            }
            cpcommit();
        }
        ull yacc[4][4] = {};
#pragma unroll 4
        for (int d = 0; d < 64; d++) {
            const float* put = &sUT[d * 132 + r0];
            ulonglong2 up0 = *(const ulonglong2*)(put);
            ulonglong2 up1 = *(const ulonglong2*)(put + 4);
            float4 gv = *(const float4*)&gbuf[d * 68 + e0];
            ull g0 = pack2(gv.x, gv.x), g1 = pack2(gv.y, gv.y);
            ull g2 = pack2(gv.z, gv.z), g3 = pack2(gv.w, gv.w);
            ffma2(yacc[0][0], up0.x, g0); ffma2(yacc[0][1], up0.x, g1);
            ffma2(yacc[0][2], up0.x, g2); ffma2(yacc[0][3], up0.x, g3);
            ffma2(yacc[1][0], up0.y, g0); ffma2(yacc[1][1], up0.y, g1);
            ffma2(yacc[1][2], up0.y, g2); ffma2(yacc[1][3], up0.y, g3);
            ffma2(yacc[2][0], up1.x, g0); ffma2(yacc[2][1], up1.x, g1);
            ffma2(yacc[2][2], up1.x, g2); ffma2(yacc[2][3], up1.x, g3);
            ffma2(yacc[3][0], up1.y, g0); ffma2(yacc[3][1], up1.y, g1);
            ffma2(yacc[3][2], up1.y, g2); ffma2(yacc[3][3], up1.y, g3);
        }
        float4 wv = *(const float4*)&sB[et * 64 + e0];
        float wj[4] = {wv.x, wv.y, wv.z, wv.w};
#pragma unroll
        for (int rp = 0; rp < 4; rp++) {
            int rA = r0 + 2 * rp;
            int oA = rA & 63, oB = (rA + 1) & 63;
            float4 cA = *(const float4*)&cbuf[oA * 68 + e0];
            float4 cB = *(const float4*)&cbuf[oB * 68 + e0];
            float cAj[4] = {cA.x, cA.y, cA.z, cA.w};
            float cBj[4] = {cB.x, cB.y, cB.z, cB.w};
#pragma unroll
            for (int j = 0; j < 4; j++) {
                float2 y = unpack2(yacc[rp][j]);
                float ya = y.x + cAj[j];
                float yb = y.y + cBj[j];
                zacc[2 * rp]     += wj[j] * rcpf(1.f + __expf(-ya));
                zacc[2 * rp + 1] += wj[j] * rcpf(1.f + __expf(-yb));
            }
        }
    }

    __syncthreads();
#pragma unroll
    for (int i = 0; i < 8; i++) sA0[(r0 + i) * 16 + tx] = zacc[i];
    __syncthreads();
    if (t < 128) {
        float z = 0.f;
#pragma unroll
        for (int q = 0; q < 16; q++) z += sA0[t * 16 + q];
        z += outb[0];
        float a = pa[0];
        out[bpair * 128 + t] = z >= 0.f ? z : a * z;
    }
}

// ---------------- launcher ----------------
extern "C" void kernel_launch(void* const* d_in, const int* in_sizes, int n_in,
                              void* d_out, int out_size) {
    const float* x   = (const float*)d_in[0];
    const float* fiW = (const float*)d_in[1];
    const float* fib = (const float*)d_in[2];
    const float* f1W = (const float*)d_in[3];
    const float* f1b = (const float*)d_in[4];
    const float* o1W = (const float*)d_in[5];
    const float* o1b = (const float*)d_in[6];
    const float* cnW = (const float*)d_in[7];
    const float* cnb = (const float*)d_in[8];
    const float* caW = (const float*)d_in[9];
    const float* oaW = (const float*)d_in[10];
    const float* ntW = (const float*)d_in[11];
    const float* gW  = (const float*)d_in[12];
    const float* omW = (const float*)d_in[13];
    const float* omb = (const float*)d_in[14];
    const float* pa  = (const float*)d_in[15];
    const float* cm  = (const float*)d_in[16];
    float* out = (float*)d_out;

    cudaFuncSetAttribute(k_final, cudaFuncAttributeMaxDynamicSharedMemorySize, 111872);

    // fat1: gemm1 split-K=5 (640) | cfcfs (256) | GT transpose (528)
    fat1<<<1424, 256, 33792>>>(x, fiW, cm, cnW, cnb, caW, gW);
    // fat2: redH1+bias+relu (2048) | csum (64)
    fat2<<<2112, 256>>>(fib);
    // fat3: gemm2 split-K=8 (128) | att (256)
    fat3<<<384, 256, 17408>>>(f1W, oaW);
    // fat4: att2 (512) | redH+bias+relu (256)
    fat4<<<768, 256>>>(ntW, f1b);
    // fat5: C gemm split-K=16 (528) | gemm3 (512)
    fat5<<<1040, 256, 17408>>>(gW, o1W, o1b);
    k_redC<<<528, 256>>>();
    k_final<<<256, 256, 111872>>>(ntW, omW, omb, pa, out);
}

// round 11
// speedup vs baseline: 1.0010x; 1.0001x over previous
#include <cuda_runtime.h>
#include <math.h>
#include <stdint.h>

// ---------------- scratch (static device globals; no allocation) ----------------
__device__ float g_h1p[5 * 512 * 1024];     // gemm1 split-K partials
__device__ float g_h1[512 * 1024];
__device__ float g_h2p[8 * 512 * 128];
__device__ float g_h2[512 * 128];
__device__ float g_hidden[512 * 4096];      // [b][o*64+d]
__device__ float g_cfs[64 * 64 * 32];       // [x][y][h]
__device__ float g_csum[64 * 32];
__device__ float g_att[64 * 2048];          // [o][i*32+g]
__device__ float g_att2[64 * 2048];         // [o][j]
__device__ float g_Cpart[16 * 64 * 2112];
__device__ float g_C[64 * 2112];            // [o][e]
__device__ float g_GT[64 * 2112];           // [d][e] = G[e][d]

typedef unsigned long long ull;

__device__ __forceinline__ ull pack2(float x, float y) {
    ull r; asm("mov.b64 %0,{%1,%2};" : "=l"(r) : "f"(x), "f"(y)); return r;
}
__device__ __forceinline__ void ffma2(ull& d, ull a, ull b) {
    asm("fma.rn.f32x2 %0,%1,%2,%0;" : "+l"(d) : "l"(a), "l"(b));
}
__device__ __forceinline__ float2 unpack2(ull v) {
    float2 r; asm("mov.b64 {%0,%1},%2;" : "=f"(r.x), "=f"(r.y) : "l"(v)); return r;
}
__device__ __forceinline__ float eluf(float x) { return x > 0.f ? x : expm1f(x); }
__device__ __forceinline__ float rcpf(float x) {
    float r; asm("rcp.approx.f32 %0,%1;" : "=f"(r) : "f"(x)); return r;
}
__device__ __forceinline__ void cpasync16(uint32_t s, const void* g) {
    asm volatile("cp.async.ca.shared.global [%0], [%1], 16;" :: "r"(s), "l"(g));
}
__device__ __forceinline__ void cpcommit() { asm volatile("cp.async.commit_group;"); }
__device__ __forceinline__ void cpwait0() { asm volatile("cp.async.wait_group 0;"); }

// ---------------- device sgemm (NT, double-buffered, f32x2) ---------------------
// C = act(A[M,K]*B[N,K]^T + bias); 64x64 tile, 256 thr, 4x4/thread; dsm: 4352 floats
__device__ __forceinline__ void dev_sgemm(
    float* dsm, int bx, int by, int bz, int nz,
    const float* __restrict__ A, const float* __restrict__ B,
    const float* __restrict__ bias, float* __restrict__ C,
    int N, int K, int lda, int ldb, int koffB, int relu, int zstride) {
    float* As = dsm;            // 2 buffers x 1088
    float* Bs = dsm + 2176;
    int t = threadIdx.x;
    int tx = t & 15, ty = t >> 4;
    int row0 = by * 64, col0 = bx * 64;
    int kPer = K / nz;
    int k0 = bz * kPer;
    const float* Ap = A + (size_t)(row0 + ty) * lda + k0 + tx;
    const float* Bp = B + (size_t)(col0 + ty) * ldb + koffB + k0 + tx;
    float ra[4], rb[4];
#pragma unroll
    for (int q = 0; q < 4; q++) {
        ra[q] = Ap[(size_t)q * 16 * lda];
        rb[q] = Bp[(size_t)q * 16 * ldb];
    }
#pragma unroll
    for (int q = 0; q < 4; q++) {
        As[tx * 68 + ty + q * 16] = ra[q];
        Bs[tx * 68 + ty + q * 16] = rb[q];
    }
    __syncthreads();
    ull acc[4][2] = {};
    int buf = 0;
    for (int kb = 16; kb <= kPer; kb += 16) {
        if (kb < kPer) {
#pragma unroll
            for (int q = 0; q < 4; q++) {
                ra[q] = Ap[kb + (size_t)q * 16 * lda];
                rb[q] = Bp[kb + (size_t)q * 16 * ldb];
            }
        }
#pragma unroll
        for (int kk = 0; kk < 16; kk++) {
            float4 av = *(const float4*)&As[buf * 1088 + kk * 68 + ty * 4];
            ulonglong2 bp = *(const ulonglong2*)&Bs[buf * 1088 + kk * 68 + tx * 4];
            ull a0 = pack2(av.x, av.x), a1 = pack2(av.y, av.y);
            ull a2 = pack2(av.z, av.z), a3 = pack2(av.w, av.w);
            ffma2(acc[0][0], a0, bp.x); ffma2(acc[0][1], a0, bp.y);
            ffma2(acc[1][0], a1, bp.x); ffma2(acc[1][1], a1, bp.y);
            ffma2(acc[2][0], a2, bp.x); ffma2(acc[2][1], a2, bp.y);
            ffma2(acc[3][0], a3, bp.x); ffma2(acc[3][1], a3, bp.y);
        }
        if (kb < kPer) {
            int nb = buf ^ 1;
#pragma unroll
            for (int q = 0; q < 4; q++) {
                As[nb * 1088 + tx * 68 + ty + q * 16] = ra[q];
                Bs[nb * 1088 + tx * 68 + ty + q * 16] = rb[q];
            }
            __syncthreads();
            buf = nb;
        }
    }
#pragma unroll
    for (int i = 0; i < 4; i++) {
        int m = row0 + ty * 4 + i;
#pragma unroll
        for (int j = 0; j < 2; j++) {
            float2 v = unpack2(acc[i][j]);
            int n = col0 + tx * 4 + 2 * j;
            if (bias) { v.x += bias[n]; v.y += bias[n + 1]; }
            if (relu) { v.x = fmaxf(v.x, 0.f); v.y = fmaxf(v.y, 0.f); }
            float* dst = C + (size_t)zstride * bz + (size_t)m * N + n;
            dst[0] = v.x;
            dst[1] = v.y;
        }
    }
}

// ---------------- device cfcfs: 16 pairs per block ------------------------------
__device__ __forceinline__ void dev_cfcfs(
    float* cawT, int pb, const float* __restrict__ cm,
    const float* __restrict__ cw, const float* __restrict__ cb,
    const float* __restrict__ caw) {
    __shared__ float sc[256], red[8], sp[256], scm[128];
    int t = threadIdx.x;
    int f = t >> 5, g = t & 31;
#pragma unroll
    for (int q = 0; q < 32; q++) {
        int l = t + q * 256;
        int ff = l >> 10, r = l & 1023, gg = r >> 5, h = r & 31;
        cawT[ff * 1056 + h * 33 + gg] = caw[l];
    }
    if (t < 128) scm[t] = cm[pb * 128 + t];
    float cwv = cw[t], cbv = cb[t];
    __syncthreads();
    for (int p = 0; p < 16; p++) {
        float m = scm[p * 8 + f];
        float v = eluf(fmaf(m, cwv, cbv));
        sc[t] = v;
        float r = expf(eluf(v));
#pragma unroll
        for (int off = 16; off; off >>= 1) r += __shfl_xor_sync(0xffffffffu, r, off);
        if (g == 0) red[f] = r;
        __syncthreads();
        float sden = 0.f;
#pragma unroll
        for (int q = 0; q < 8; q++) sden += red[q];
        float lin = 0.f;
#pragma unroll
        for (int h = 0; h < 32; h++) lin = fmaf(sc[f * 32 + h], cawT[f * 1056 + h * 33 + g], lin);
        float E = expf(eluf(v));
        sp[t] = eluf(E * lin / sden);
        __syncthreads();
        if (t < 32) {
            float sum = 0.f;
#pragma unroll
            for (int ff2 = 0; ff2 < 8; ff2++) sum += sp[ff2 * 32 + t];
            g_cfs[(pb * 16 + p) * 32 + t] = eluf(sum * 0.125f);
        }
        __syncthreads();
    }
}

// ---------------- fat1: gemm1 split-K=5 | cfcfs | GT transpose ------------------
__global__ __launch_bounds__(256) void fat1(
    const float* __restrict__ x, const float* __restrict__ fiW,
    const float* __restrict__ cm, const float* __restrict__ cw,
    const float* __restrict__ cb, const float* __restrict__ caw,
    const float* __restrict__ G) {
    extern __shared__ __align__(16) float dsm[];
    int b = blockIdx.x;
    if (b < 640) {
        int bx = b % 16, by = (b / 16) % 8, bz = b / 128;
        dev_sgemm(dsm, bx, by, bz, 5, x, fiW, nullptr, g_h1p,
                  1024, 2000, 2000, 2000, 0, 0, 524288);
    } else if (b < 896) {
        dev_cfcfs(dsm, b - 640, cm, cw, cb, caw);
    } else {
        int i = (b - 896) * 256 + threadIdx.x;   // 135168
        int d = i / 2112, e = i % 2112;
        g_GT[i] = G[(size_t)e * 2112 + d];
    }
}

// ---------------- fat2: redH1 (+bias+relu) | csum -------------------------------
__global__ __launch_bounds__(256) void fat2(const float* __restrict__ fib) {
    int b = blockIdx.x;
    int t = threadIdx.x;
    if (b < 2048) {
        int idx = b * 256 + t;                   // 524288
        float s = 0.f;
#pragma unroll
        for (int z = 0; z < 5; z++) s += g_h1p[z * 524288 + idx];
        g_h1[idx] = fmaxf(s + fib[idx & 1023], 0.f);
    } else {
        int xq = b - 2048;                       // 64
        int ys = t >> 5, h = t & 31;
        float s = 0.f;
        for (int y = ys; y < 64; y += 8) s += expf(eluf(g_cfs[(xq * 64 + y) * 32 + h]));
        __shared__ float r[256];
        r[t] = s;
        __syncthreads();
        if (t < 32) {
            float a = 0.f;
#pragma unroll
            for (int q = 0; q < 8; q++) a += r[q * 32 + t];
            g_csum[xq * 32 + t] = a;
        }
    }
}

// ---------------- fat3: gemm2 split-K=8 | att ------------------------------------
__global__ __launch_bounds__(256) void fat3(const float* __restrict__ f1W,
                                            const float* __restrict__ oaw) {
    extern __shared__ __align__(16) float dsm[];
    int b = blockIdx.x;
    int t = threadIdx.x;
    if (b < 128) {
        int bx = b % 2, by = (b / 2) % 8, bz = b / 16;
        dev_sgemm(dsm, bx, by, bz, 8, g_h1, f1W, nullptr, g_h2p,
                  128, 1024, 1024, 1024, 0, 0, 65536);
    } else {
        int bq = b - 128;                        // 256
        int i = bq >> 2, og = bq & 3;
        int osub = t >> 5, g = t & 31;
        __shared__ float sw[32 * 33];
        __shared__ float scf[16 * 32];
#pragma unroll
        for (int q = 0; q < 4; q++) {
            int l = t + q * 256;
            int gg = l >> 5, h = l & 31;
            sw[h * 33 + gg] = oaw[i * 1024 + l];
        }
#pragma unroll
        for (int q = 0; q < 2; q++) {
            int l = t + q * 256;
            int op = l >> 5, h = l & 31;
            scf[l] = g_cfs[((og * 16 + op) * 64 + i) * 32 + h];
        }
        __syncthreads();
#pragma unroll
        for (int q = 0; q < 2; q++) {
            int op = osub * 2 + q;
            int o = og * 16 + op;
            float lin = 0.f;
#pragma unroll
            for (int h = 0; h < 32; h++) lin = fmaf(scf[op * 32 + h], sw[h * 33 + g], lin);
            float E = expf(eluf(scf[op * 32 + g]));
            g_att[o * 2048 + i * 32 + g] = E / g_csum[o * 32 + g] * lin;
        }
    }
}

// ---------------- fat4: att2 | redH (+bias+relu) ---------------------------------
__global__ __launch_bounds__(256) void fat4(const float* __restrict__ wnt,
                                            const float* __restrict__ f1b) {
    int b = blockIdx.x;
    int t = threadIdx.x;
    if (b < 512) {
        int idx = b * 256 + t;                   // 131072
        int o = idx >> 11, j = idx & 2047;
        float acc = 0.f;
#pragma unroll 8
        for (int p = 0; p < 64; p++) acc += wnt[o * 64 + p] * g_att[p * 2048 + j];
        g_att2[idx] = acc;
    } else {
        int idx = (b - 512) * 256 + t;           // 65536
        float s = 0.f;
#pragma unroll
        for (int z = 0; z < 8; z++) s += g_h2p[z * 65536 + idx];
        g_h2[idx] = fmaxf(s + f1b[idx & 127], 0.f);
    }
}

// ---------------- fat5: C gemm split-K=16 | gemm3 --------------------------------
__global__ __launch_bounds__(256) void fat5(const float* __restrict__ gW,
                                            const float* __restrict__ o1W,
                                            const float* __restrict__ o1b) {
    extern __shared__ __align__(16) float dsm[];
    int b = blockIdx.x;
    if (b < 528) {
        int bx = b % 33, bz = b / 33;
        dev_sgemm(dsm, bx, 0, bz, 16, g_att2, gW, nullptr, g_Cpart,
                  2112, 2048, 2048, 2112, 64, 0, 135168);
    } else {
        int r = b - 528;                         // 512
        int bx = r % 64, by = r / 64;
        dev_sgemm(dsm, bx, by, 0, 1, g_h2, o1W, o1b, g_hidden,
                  4096, 128, 128, 128, 0, 1, 0);
    }
}

// deterministic split-K reduce for C
__global__ void k_redC() {
    int i = blockIdx.x * 256 + threadIdx.x;     // 135168
    float s = 0.f;
#pragma unroll
    for (int z = 0; z < 16; z++) s += g_Cpart[z * 135168 + i];
    g_C[i] = s;
}

// ---------------- fused final: U + y GEMM + sigmoid + weighted reduce ----------
__global__ __launch_bounds__(256, 2) void k_final(
    const float* __restrict__ Wnt, const float* __restrict__ wout,
    const float* __restrict__ outb, const float* __restrict__ pa,
    float* __restrict__ out) {
    extern __shared__ __align__(16) float smem[];
    float* sUT = smem;               // 8448
    float* sA0 = sUT + 8448;         // 4352
    float* sA1 = sA0 + 4352;         // 4352
    float* sB  = sA1 + 4352;         // 2112
    float* sC0 = sB + 2112;          // 4352
    float* sC1 = sC0 + 4352;         // 4352
    const float* GT = g_GT;
    const float* Cg = g_C;
    int t = threadIdx.x;
    int tx = t & 15, ty = t >> 4;
    int bpair = blockIdx.x;
    uint32_t sA0u = (uint32_t)__cvta_generic_to_shared(sA0);
    uint32_t sA1u = (uint32_t)__cvta_generic_to_shared(sA1);
    uint32_t sC0u = (uint32_t)__cvta_generic_to_shared(sC0);
    uint32_t sC1u = (uint32_t)__cvta_generic_to_shared(sC1);

    // prefetch G tile 0 -> sA1 (overlaps the whole U phase)
#pragma unroll
    for (int q = 0; q < 4; q++) {
        int u = t + q * 256;
        int d = u >> 4, e4 = u & 15;
        cpasync16(sA1u + (d * 68 + e4 * 4) * 4, GT + (size_t)d * 2112 + e4 * 4);
    }
    cpcommit();

    // stage Wnt transposed: sA0[p][o]
#pragma unroll
    for (int q = 0; q < 16; q++) {
        int l = t + q * 256;
        int o = l >> 6, p = l & 63;
        sA0[p * 68 + o] = Wnt[l];
    }

    for (int bb = 0; bb < 2; bb++) {
        const float4* hid = (const float4*)(g_hidden + (size_t)(2 * bpair + bb) * 4096);
#pragma unroll
        for (int q = 0; q < 4; q++) {
            int l4 = t + q * 256;
            int p = l4 >> 4, d = (l4 & 15) * 4;
            *(float4*)&sC0[p * 68 + d] = hid[l4];
        }
        __syncthreads();
        ull uacc[4][2] = {};
#pragma unroll 8
        for (int p = 0; p < 64; p++) {
            float4 av = *(const float4*)&sA0[p * 68 + ty * 4];
            ulonglong2 bp2 = *(const ulonglong2*)&sC0[p * 68 + tx * 4];
            ull a0 = pack2(av.x, av.x), a1 = pack2(av.y, av.y);
            ull a2 = pack2(av.z, av.z), a3 = pack2(av.w, av.w);
            ffma2(uacc[0][0], a0, bp2.x); ffma2(uacc[0][1], a0, bp2.y);
            ffma2(uacc[1][0], a1, bp2.x); ffma2(uacc[1][1], a1, bp2.y);
            ffma2(uacc[2][0], a2, bp2.x); ffma2(uacc[2][1], a2, bp2.y);
            ffma2(uacc[3][0], a3, bp2.x); ffma2(uacc[3][1], a3, bp2.y);
        }
#pragma unroll
        for (int i = 0; i < 4; i++) {
            int o = ty * 4 + i;
#pragma unroll
            for (int j = 0; j < 2; j++) {
                float2 v = unpack2(uacc[i][j]);
                int d = tx * 4 + 2 * j;
                sUT[d * 132 + bb * 64 + o] = v.x;
                sUT[(d + 1) * 132 + bb * 64 + o] = v.y;
            }
        }
        __syncthreads();
    }

    // sC0 free now: prefetch C tile 0
#pragma unroll
    for (int q = 0; q < 4; q++) {
        int u = t + q * 256;
        int o = u >> 4, e4 = u & 15;
        cpasync16(sC0u + (o * 68 + e4 * 4) * 4, Cg + (size_t)o * 2112 + e4 * 4);
    }
    cpcommit();

    // stage wout
    for (int l = t; l < 2112; l += 256) sB[l] = wout[l];

    float zacc[8] = {0.f, 0.f, 0.f, 0.f, 0.f, 0.f, 0.f, 0.f};
    int r0 = ty * 8, e0 = tx * 4;

    for (int et = 0; et < 33; et++) {
        cpwait0();
        __syncthreads();
        float* gbuf = (et & 1) ? sA0 : sA1;
        float* cbuf = (et & 1) ? sC1 : sC0;
        if (et < 32) {
            uint32_t gd = (et & 1) ? sA1u : sA0u;
            uint32_t cd = (et & 1) ? sC0u : sC1u;
            const float* gsrc = GT + (et + 1) * 64;
            const float* csrc = Cg + (et + 1) * 64;
#pragma unroll
            for (int q = 0; q < 4; q++) {
                int u = t + q * 256;
                int r = u >> 4, e4 = u & 15;
                cpasync16(gd + (r * 68 + e4 * 4) * 4, gsrc + (size_t)r * 2112 + e4 * 4);
                cpasync16(cd + (r * 68 + e4 * 4) * 4, csrc + (size_t)r * 2112 + e4 * 4);
            }
            cpcommit();
        }
        ull yacc[4][4] = {};
#pragma unroll 4
        for (int d = 0; d < 64; d++) {
            const float* put = &sUT[d * 132 + r0];
            ulonglong2 up0 = *(const ulonglong2*)(put);
            ulonglong2 up1 = *(const ulonglong2*)(put + 4);
            float4 gv = *(const float4*)&gbuf[d * 68 + e0];
            ull g0 = pack2(gv.x, gv.x), g1 = pack2(gv.y, gv.y);
            ull g2 = pack2(gv.z, gv.z), g3 = pack2(gv.w, gv.w);
            ffma2(yacc[0][0], up0.x, g0); ffma2(yacc[0][1], up0.x, g1);
            ffma2(yacc[0][2], up0.x, g2); ffma2(yacc[0][3], up0.x, g3);
            ffma2(yacc[1][0], up0.y, g0); ffma2(yacc[1][1], up0.y, g1);
            ffma2(yacc[1][2], up0.y, g2); ffma2(yacc[1][3], up0.y, g3);
            ffma2(yacc[2][0], up1.x, g0); ffma2(yacc[2][1], up1.x, g1);
            ffma2(yacc[2][2], up1.x, g2); ffma2(yacc[2][3], up1.x, g3);
            ffma2(yacc[3][0], up1.y, g0); ffma2(yacc[3][1], up1.y, g1);
            ffma2(yacc[3][2], up1.y, g2); ffma2(yacc[3][3], up1.y, g3);
        }
        float4 wv = *(const float4*)&sB[et * 64 + e0];
        float wj[4] = {wv.x, wv.y, wv.z, wv.w};
#pragma unroll
        for (int rp = 0; rp < 4; rp++) {
            int rA = r0 + 2 * rp;
            int oA = rA & 63, oB = (rA + 1) & 63;
            float4 cA = *(const float4*)&cbuf[oA * 68 + e0];
            float4 cB = *(const float4*)&cbuf[oB * 68 + e0];
            float cAj[4] = {cA.x, cA.y, cA.z, cA.w};
            float cBj[4] = {cB.x, cB.y, cB.z, cB.w};
#pragma unroll
            for (int j = 0; j < 4; j++) {
                float2 y = unpack2(yacc[rp][j]);
                float ya = y.x + cAj[j];
                float yb = y.y + cBj[j];
                zacc[2 * rp]     += wj[j] * rcpf(1.f + __expf(-ya));
                zacc[2 * rp + 1] += wj[j] * rcpf(1.f + __expf(-yb));
            }
        }
    }

    __syncthreads();
#pragma unroll
    for (int i = 0; i < 8; i++) sA0[(r0 + i) * 16 + tx] = zacc[i];
    __syncthreads();
    if (t < 128) {
        float z = 0.f;
#pragma unroll
        for (int q = 0; q < 16; q++) z += sA0[t * 16 + q];
        z += outb[0];
        float a = pa[0];
        out[bpair * 128 + t] = z >= 0.f ? z : a * z;
    }
}

// ---------------- launcher ----------------
extern "C" void kernel_launch(void* const* d_in, const int* in_sizes, int n_in,
                              void* d_out, int out_size) {
    const float* x   = (const float*)d_in[0];
    const float* fiW = (const float*)d_in[1];
    const float* fib = (const float*)d_in[2];
    const float* f1W = (const float*)d_in[3];
    const float* f1b = (const float*)d_in[4];
    const float* o1W = (const float*)d_in[5];
    const float* o1b = (const float*)d_in[6];
    const float* cnW = (const float*)d_in[7];
    const float* cnb = (const float*)d_in[8];
    const float* caW = (const float*)d_in[9];
    const float* oaW = (const float*)d_in[10];
    const float* ntW = (const float*)d_in[11];
    const float* gW  = (const float*)d_in[12];
    const float* omW = (const float*)d_in[13];
    const float* omb = (const float*)d_in[14];
    const float* pa  = (const float*)d_in[15];
    const float* cm  = (const float*)d_in[16];
    float* out = (float*)d_out;

    cudaFuncSetAttribute(k_final, cudaFuncAttributeMaxDynamicSharedMemorySize, 111872);

    // fat1: gemm1 split-K=5 (640) | cfcfs (256) | GT transpose (528)
    fat1<<<1424, 256, 33792>>>(x, fiW, cm, cnW, cnb, caW, gW);
    // fat2: redH1+bias+relu (2048) | csum (64)
    fat2<<<2112, 256>>>(fib);
    // fat3: gemm2 split-K=8 (128) | att (256)
    fat3<<<384, 256, 17408>>>(f1W, oaW);
    // fat4: att2 (512) | redH+bias+relu (256)
    fat4<<<768, 256>>>(ntW, f1b);
    // fat5: C gemm split-K=16 (528) | gemm3 (512)
    fat5<<<1040, 256, 17408>>>(gW, o1W, o1b);
    k_redC<<<528, 256>>>();
    k_final<<<256, 256, 111872>>>(ntW, omW, omb, pa, out);
}

// round 15
// speedup vs baseline: 1.3675x; 1.3661x over previous
#include <cuda_runtime.h>
#include <cuda_bf16.h>
#include <math.h>
#include <stdint.h>

__device__ float g_h1p[5 * 512 * 1024];
__device__ float g_h1[512 * 1024];
__device__ float g_h2p[8 * 512 * 128];
__device__ float g_h2[512 * 128];
__device__ __align__(16) float g_hidden[512 * 4096];
__device__ float g_cfs[64 * 64 * 32];
__device__ float g_csum[64 * 32];
__device__ float g_att[64 * 2048];
__device__ float g_att2[64 * 2048];
__device__ float g_Cpart[16 * 64 * 2112];
__device__ __align__(16) float g_C[64 * 2112];
__device__ __align__(16) uint16_t g_Uhi[32768 * 64];
__device__ __align__(16) uint16_t g_Ulo[32768 * 64];
__device__ __align__(16) uint16_t g_Ghi[2112 * 64];
__device__ __align__(16) uint16_t g_Glo[2112 * 64];
__device__ float g_zp[11 * 32768];

typedef unsigned long long ull;

__device__ __forceinline__ ull pack2(float x, float y) {
    ull r; asm("mov.b64 %0,{%1,%2};" : "=l"(r) : "f"(x), "f"(y)); return r;
}
__device__ __forceinline__ void ffma2(ull& d, ull a, ull b) {
    asm("fma.rn.f32x2 %0,%1,%2,%0;" : "+l"(d) : "l"(a), "l"(b));
}
__device__ __forceinline__ float2 unpack2(ull v) {
    float2 r; asm("mov.b64 {%0,%1},%2;" : "=f"(r.x), "=f"(r.y) : "l"(v)); return r;
}
__device__ __forceinline__ float eluf(float x) { return x > 0.f ? x : expm1f(x); }
__device__ __forceinline__ float rcpf(float x) {
    float r; asm("rcp.approx.f32 %0,%1;" : "=f"(r) : "f"(x)); return r;
}
__device__ __forceinline__ void cpasync16(uint32_t s, const void* g) {
    asm volatile("cp.async.ca.shared.global [%0], [%1], 16;" :: "r"(s), "l"(g));
}
__device__ __forceinline__ void cpcommit() { asm volatile("cp.async.commit_group;"); }
__device__ __forceinline__ void cpwait0() { asm volatile("cp.async.wait_group 0;"); }
__device__ __forceinline__ uint32_t smem_u32(const void* p) {
    return (uint32_t)__cvta_generic_to_shared(p);
}
__device__ __forceinline__ uint16_t f2bf(float x) {
    return __bfloat16_as_ushort(__float2bfloat16(x));
}
__device__ __forceinline__ float bf2f(uint16_t u) {
    return __bfloat162float(__ushort_as_bfloat16(u));
}
#define SWZ(x) ((x) ^ (((x) >> 3) & 0x70))

// ---- base-ISA tensor ops: ldmatrix + mma.sync (bf16 -> f32) --------------------
__device__ __forceinline__ void ldmatrix_x4(uint32_t* r, uint32_t addr) {
    asm volatile("ldmatrix.sync.aligned.m8n8.x4.shared.b16 {%0,%1,%2,%3}, [%4];"
                 : "=r"(r[0]), "=r"(r[1]), "=r"(r[2]), "=r"(r[3]) : "r"(addr));
}
__device__ __forceinline__ void ldmatrix_x2(uint32_t& r0, uint32_t& r1, uint32_t addr) {
    asm volatile("ldmatrix.sync.aligned.m8n8.x2.shared.b16 {%0,%1}, [%2];"
                 : "=r"(r0), "=r"(r1) : "r"(addr));
}
__device__ __forceinline__ void mma_bf16(float& d0, float& d1, float& d2, float& d3,
                                         const uint32_t* a, uint32_t b0, uint32_t b1) {
    asm volatile(
        "mma.sync.aligned.m16n8k16.row.col.f32.bf16.bf16.f32 "
        "{%0,%1,%2,%3},{%4,%5,%6,%7},{%8,%9},{%0,%1,%2,%3};"
        : "+f"(d0), "+f"(d1), "+f"(d2), "+f"(d3)
        : "r"(a[0]), "r"(a[1]), "r"(a[2]), "r"(a[3]), "r"(b0), "r"(b1));
}

// ---- f32x2 NT sgemm (64x64 tile, 256 thr, double-buffered); dsm 4352 floats ----
__device__ __forceinline__ void dev_sgemm(
    float* dsm, int bx, int by, int bz, int nz,
    const float* __restrict__ A, const float* __restrict__ B,
    const float* __restrict__ bias, float* __restrict__ C,
    int N, int K, int lda, int ldb, int koffB, int relu, int zstride) {
    float* As = dsm;
    float* Bs = dsm + 2176;
    int t = threadIdx.x, tx = t & 15, ty = t >> 4;
    int row0 = by * 64, col0 = bx * 64;
    int kPer = K / nz, k0 = bz * kPer;
    const float* Ap = A + (size_t)(row0 + ty) * lda + k0 + tx;
    const float* Bp = B + (size_t)(col0 + ty) * ldb + koffB + k0 + tx;
    float ra[4], rb[4];
#pragma unroll
    for (int q = 0; q < 4; q++) { ra[q] = Ap[(size_t)q * 16 * lda]; rb[q] = Bp[(size_t)q * 16 * ldb]; }
#pragma unroll
    for (int q = 0; q < 4; q++) { As[tx * 68 + ty + q * 16] = ra[q]; Bs[tx * 68 + ty + q * 16] = rb[q]; }
    __syncthreads();
    ull acc[4][2] = {};
    int buf = 0;
    for (int kb = 16; kb <= kPer; kb += 16) {
        if (kb < kPer) {
#pragma unroll
            for (int q = 0; q < 4; q++) { ra[q] = Ap[kb + (size_t)q * 16 * lda]; rb[q] = Bp[kb + (size_t)q * 16 * ldb]; }
        }
#pragma unroll
        for (int kk = 0; kk < 16; kk++) {
            float4 av = *(const float4*)&As[buf * 1088 + kk * 68 + ty * 4];
            ulonglong2 bp = *(const ulonglong2*)&Bs[buf * 1088 + kk * 68 + tx * 4];
            ull a0 = pack2(av.x, av.x), a1 = pack2(av.y, av.y);
            ull a2 = pack2(av.z, av.z), a3 = pack2(av.w, av.w);
            ffma2(acc[0][0], a0, bp.x); ffma2(acc[0][1], a0, bp.y);
            ffma2(acc[1][0], a1, bp.x); ffma2(acc[1][1], a1, bp.y);
            ffma2(acc[2][0], a2, bp.x); ffma2(acc[2][1], a2, bp.y);
            ffma2(acc[3][0], a3, bp.x); ffma2(acc[3][1], a3, bp.y);
        }
        if (kb < kPer) {
            int nb = buf ^ 1;
#pragma unroll
            for (int q = 0; q < 4; q++) {
                As[nb * 1088 + tx * 68 + ty + q * 16] = ra[q];
                Bs[nb * 1088 + tx * 68 + ty + q * 16] = rb[q];
            }
            __syncthreads();
            buf = nb;
        }
    }
#pragma unroll
    for (int i = 0; i < 4; i++) {
        int m = row0 + ty * 4 + i;
#pragma unroll
        for (int j = 0; j < 2; j++) {
            float2 v = unpack2(acc[i][j]);
            int n = col0 + tx * 4 + 2 * j;
            if (bias) { v.x += bias[n]; v.y += bias[n + 1]; }
            if (relu) { v.x = fmaxf(v.x, 0.f); v.y = fmaxf(v.y, 0.f); }
            float* dst = C + (size_t)zstride * bz + (size_t)m * N + n;
            dst[0] = v.x; dst[1] = v.y;
        }
    }
}

__device__ __forceinline__ void dev_cfcfs(
    float* cawT, int pb, const float* __restrict__ cm,
    const float* __restrict__ cw, const float* __restrict__ cb,
    const float* __restrict__ caw) {
    __shared__ float sc[256], red[8], sp[256], scm[128];
    int t = threadIdx.x, f = t >> 5, g = t & 31;
#pragma unroll
    for (int q = 0; q < 32; q++) {
        int l = t + q * 256;
        int ff = l >> 10, r = l & 1023, gg = r >> 5, h = r & 31;
        cawT[ff * 1056 + h * 33 + gg] = caw[l];
    }
    if (t < 128) scm[t] = cm[pb * 128 + t];
    float cwv = cw[t], cbv = cb[t];
    __syncthreads();
    for (int p = 0; p < 16; p++) {
        float m = scm[p * 8 + f];
        float v = eluf(fmaf(m, cwv, cbv));
        sc[t] = v;
        float r = expf(eluf(v));
#pragma unroll
        for (int off = 16; off; off >>= 1) r += __shfl_xor_sync(0xffffffffu, r, off);
        if (g == 0) red[f] = r;
        __syncthreads();
        float sden = 0.f;
#pragma unroll
        for (int q = 0; q < 8; q++) sden += red[q];
        float lin = 0.f;
#pragma unroll
        for (int h = 0; h < 32; h++) lin = fmaf(sc[f * 32 + h], cawT[f * 1056 + h * 33 + g], lin);
        float E = expf(eluf(v));
        sp[t] = eluf(E * lin / sden);
        __syncthreads();
        if (t < 32) {
            float sum = 0.f;
#pragma unroll
            for (int ff2 = 0; ff2 < 8; ff2++) sum += sp[ff2 * 32 + t];
            g_cfs[(pb * 16 + p) * 32 + t] = eluf(sum * 0.125f);
        }
        __syncthreads();
    }
}

// fat1: gemm1 split-K=5 | cfcfs | G bf16 split
__global__ __launch_bounds__(256) void fat1(
    const float* __restrict__ x, const float* __restrict__ fiW,
    const float* __restrict__ cm, const float* __restrict__ cw,
    const float* __restrict__ cb, const float* __restrict__ caw,
    const float* __restrict__ G) {
    extern __shared__ __align__(16) float dsm[];
    int b = blockIdx.x;
    if (b < 640) {
        int bx = b % 16, by = (b / 16) % 8, bz = b / 128;
        dev_sgemm(dsm, bx, by, bz, 5, x, fiW, nullptr, g_h1p, 1024, 2000, 2000, 2000, 0, 0, 524288);
    } else if (b < 896) {
        dev_cfcfs(dsm, b - 640, cm, cw, cb, caw);
    } else {
        int i = (b - 896) * 256 + threadIdx.x;   // 135168 = 2112*64
        int e = i >> 6, d = i & 63;
        float v = G[(size_t)e * 2112 + d];
        uint16_t hi = f2bf(v);
        g_Ghi[i] = hi;
        g_Glo[i] = f2bf(v - bf2f(hi));
    }
}

// fat2: redH1(+bias+relu) | csum
__global__ __launch_bounds__(256) void fat2(const float* __restrict__ fib) {
    int b = blockIdx.x, t = threadIdx.x;
    if (b < 2048) {
        int idx = b * 256 + t;
        float s = 0.f;
#pragma unroll
        for (int z = 0; z < 5; z++) s += g_h1p[z * 524288 + idx];
        g_h1[idx] = fmaxf(s + fib[idx & 1023], 0.f);
    } else {
        int xq = b - 2048;
        int ys = t >> 5, h = t & 31;
        float s = 0.f;
        for (int y = ys; y < 64; y += 8) s += expf(eluf(g_cfs[(xq * 64 + y) * 32 + h]));
        __shared__ float r[256];
        r[t] = s;
        __syncthreads();
        if (t < 32) {
            float a = 0.f;
#pragma unroll
            for (int q = 0; q < 8; q++) a += r[q * 32 + t];
            g_csum[xq * 32 + t] = a;
        }
    }
}

// fat3: gemm2 split-K=8 | att
__global__ __launch_bounds__(256) void fat3(const float* __restrict__ f1W,
                                            const float* __restrict__ oaw) {
    extern __shared__ __align__(16) float dsm[];
    int b = blockIdx.x, t = threadIdx.x;
    if (b < 128) {
        int bx = b % 2, by = (b / 2) % 8, bz = b / 16;
        dev_sgemm(dsm, bx, by, bz, 8, g_h1, f1W, nullptr, g_h2p, 128, 1024, 1024, 1024, 0, 0, 65536);
    } else {
        int bq = b - 128;
        int i = bq >> 2, og = bq & 3;
        int osub = t >> 5, g = t & 31;
        __shared__ float sw[32 * 33];
        __shared__ float scf[16 * 32];
#pragma unroll
        for (int q = 0; q < 4; q++) {
            int l = t + q * 256;
            sw[(l & 31) * 33 + (l >> 5)] = oaw[i * 1024 + l];
        }
#pragma unroll
        for (int q = 0; q < 2; q++) {
            int l = t + q * 256;
            scf[l] = g_cfs[((og * 16 + (l >> 5)) * 64 + i) * 32 + (l & 31)];
        }
        __syncthreads();
#pragma unroll
        for (int q = 0; q < 2; q++) {
            int op = osub * 2 + q;
            int o = og * 16 + op;
            float lin = 0.f;
#pragma unroll
            for (int h = 0; h < 32; h++) lin = fmaf(scf[op * 32 + h], sw[h * 33 + g], lin);
            float E = expf(eluf(scf[op * 32 + g]));
            g_att[o * 2048 + i * 32 + g] = E / g_csum[o * 32 + g] * lin;
        }
    }
}

// fat4: att2 | redH(+bias+relu)
__global__ __launch_bounds__(256) void fat4(const float* __restrict__ wnt,
                                            const float* __restrict__ f1b) {
    int b = blockIdx.x, t = threadIdx.x;
    if (b < 512) {
        int idx = b * 256 + t;
        int o = idx >> 11, j = idx & 2047;
        float acc = 0.f;
#pragma unroll 8
        for (int p = 0; p < 64; p++) acc += wnt[o * 64 + p] * g_att[p * 2048 + j];
        g_att2[idx] = acc;
    } else {
        int idx = (b - 512) * 256 + t;
        float s = 0.f;
#pragma unroll
        for (int z = 0; z < 8; z++) s += g_h2p[z * 65536 + idx];
        g_h2[idx] = fmaxf(s + f1b[idx & 127], 0.f);
    }
}

// fat5: C gemm split-K=16 | gemm3
__global__ __launch_bounds__(256) void fat5(const float* __restrict__ gW,
                                            const float* __restrict__ o1W,
                                            const float* __restrict__ o1b) {
    extern __shared__ __align__(16) float dsm[];
    int b = blockIdx.x;
    if (b < 528) {
        dev_sgemm(dsm, b % 33, 0, b / 33, 16, g_att2, gW, nullptr, g_Cpart, 2112, 2048, 2048, 2112, 64, 0, 135168);
    } else {
        int r = b - 528;
        dev_sgemm(dsm, r % 64, r / 64, 0, 1, g_h2, o1W, o1b, g_hidden, 4096, 128, 128, 128, 0, 1, 0);
    }
}

// fat6: redC | uprep (U = Wnt@hidden, bf16 hi/lo split)
__global__ __launch_bounds__(256) void fat6(const float* __restrict__ Wnt) {
    extern __shared__ __align__(16) float dsm[];
    int b = blockIdx.x, t = threadIdx.x;
    if (b < 528) {
        int i = b * 256 + t;
        float s = 0.f;
#pragma unroll
        for (int z = 0; z < 16; z++) s += g_Cpart[z * 135168 + i];
        g_C[i] = s;
        return;
    }
    int bpair = b - 528;
    float* sA = dsm;            // 4352: WntT[p][o]
    float* sB = dsm + 4352;     // 4352: hidden[p][d]
    int tx = t & 15, ty = t >> 4;
#pragma unroll
    for (int q = 0; q < 16; q++) {
        int l = t + q * 256;
        sA[(l & 63) * 68 + (l >> 6)] = Wnt[l];
    }
    for (int bb = 0; bb < 2; bb++) {
        int bidx = 2 * bpair + bb;
        const float4* hid = (const float4*)(g_hidden + (size_t)bidx * 4096);
#pragma unroll
        for (int q = 0; q < 4; q++) {
            int l4 = t + q * 256;
            *(float4*)&sB[(l4 >> 4) * 68 + (l4 & 15) * 4] = hid[l4];
        }
        __syncthreads();
        ull uacc[4][2] = {};
#pragma unroll 8
        for (int p = 0; p < 64; p++) {
            float4 av = *(const float4*)&sA[p * 68 + ty * 4];
            ulonglong2 bp2 = *(const ulonglong2*)&sB[p * 68 + tx * 4];
            ull a0 = pack2(av.x, av.x), a1 = pack2(av.y, av.y);
            ull a2 = pack2(av.z, av.z), a3 = pack2(av.w, av.w);
            ffma2(uacc[0][0], a0, bp2.x); ffma2(uacc[0][1], a0, bp2.y);
            ffma2(uacc[1][0], a1, bp2.x); ffma2(uacc[1][1], a1, bp2.y);
            ffma2(uacc[2][0], a2, bp2.x); ffma2(uacc[2][1], a2, bp2.y);
            ffma2(uacc[3][0], a3, bp2.x); ffma2(uacc[3][1], a3, bp2.y);
        }
#pragma unroll
        for (int i = 0; i < 4; i++) {
            int row = bidx * 64 + ty * 4 + i;
#pragma unroll
            for (int j = 0; j < 2; j++) {
                float2 v = unpack2(uacc[i][j]);
                int d = tx * 4 + 2 * j;
                uint16_t hx = f2bf(v.x), hy = f2bf(v.y);
                *(uint32_t*)&g_Uhi[(size_t)row * 64 + d] = (uint32_t)hx | ((uint32_t)hy << 16);
                *(uint32_t*)&g_Ulo[(size_t)row * 64 + d] =
                    (uint32_t)f2bf(v.x - bf2f(hx)) | ((uint32_t)f2bf(v.y - bf2f(hy)) << 16);
            }
        }
        __syncthreads();
    }
}

// k_ftc: mma.sync bf16x3  Y = U*G^T (C preloaded into accumulators)
//        -> sigmoid -> weighted z partials.
// grid = 256 m-tiles x 11 n-chunks; M=128 rows, chunk = 192 e, K=64.
// SMEM (dyn, 128B aligned): Uhi 16K | Ulo 16K | Ghi 24K | Glo 24K (SW128 rows of 128B)
__global__ __launch_bounds__(256) void k_ftc(const float* __restrict__ wout) {
    extern __shared__ __align__(16) float dyn[];
    __shared__ float sww[192];
    int t = threadIdx.x, w = t >> 5, lane = t & 31;
    int mt = blockIdx.x / 11, nch = blockIdx.x % 11;
    int mrow0 = mt * 128, n0 = nch * 192;
    uint32_t sb = (smem_u32(dyn) + 127) & ~127u;
    uint32_t sbUhi = sb, sbUlo = sb + 16384, sbGhi = sb + 32768, sbGlo = sb + 57344;

    // stage U tile: 128 rows x 64 bf16 (hi+lo) = 2048 16B units
#pragma unroll
    for (int q = 0; q < 8; q++) {
        int u = q * 256 + t;
        int half = u >> 10, uu = u & 1023;
        int row = uu >> 3, c = uu & 7;
        const uint16_t* src = (half ? g_Ulo : g_Uhi) + (size_t)(mrow0 + row) * 64 + c * 8;
        cpasync16((half ? sbUlo : sbUhi) + SWZ((uint32_t)(row * 128 + c * 16)), src);
    }
    // stage G chunk: 192 rows x 64 bf16 (hi+lo) = 3072 units
#pragma unroll
    for (int q = 0; q < 12; q++) {
        int u = q * 256 + t;
        int half = (u >= 1536) ? 1 : 0;
        int uu = u - half * 1536;
        int row = uu >> 3, c = uu & 7;
        const uint16_t* src = (half ? g_Glo : g_Ghi) + (size_t)(n0 + row) * 64 + c * 8;
        cpasync16((half ? sbGlo : sbGhi) + SWZ((uint32_t)(row * 128 + c * 16)), src);
    }
    cpcommit();
    if (t < 192) sww[t] = wout[n0 + t];
    cpwait0();
    __syncthreads();

    // A fragments: rows w*16..w*16+15, 4 k-steps of 16; held in registers
    uint32_t Ahi[4][4], Alo[4][4];
    {
        int mrow = w * 16 + (lane & 15);
        uint32_t koff = (uint32_t)(lane >> 4) * 16;
#pragma unroll
        for (int ks = 0; ks < 4; ks++) {
            uint32_t off = SWZ((uint32_t)(mrow * 128 + ks * 32) + koff);
            ldmatrix_x4(Ahi[ks], sbUhi + off);
            ldmatrix_x4(Alo[ks], sbUlo + off);
        }
    }

    int gid = lane >> 2, tig = lane & 3;
    int o1 = (w * 16 + gid) & 63, o2 = (w * 16 + gid + 8) & 63;
    float z0 = 0.f, z1 = 0.f;
    // prefetch C for n8-tile 0
    float2 c01 = *(const float2*)&g_C[o1 * 2112 + n0 + tig * 2];
    float2 c23 = *(const float2*)&g_C[o2 * 2112 + n0 + tig * 2];
    uint32_t brow = (uint32_t)(lane & 7) * 128 + (uint32_t)((lane >> 3) & 1) * 16;

    for (int n8 = 0; n8 < 24; n8++) {
        float a0 = c01.x, a1 = c01.y, a2 = c23.x, a3 = c23.y;
        if (n8 < 23) {
            int ngn = n0 + (n8 + 1) * 8 + tig * 2;
            c01 = *(const float2*)&g_C[o1 * 2112 + ngn];
            c23 = *(const float2*)&g_C[o2 * 2112 + ngn];
        }
        uint32_t base = (uint32_t)(n8 * 8) * 128 + brow;
#pragma unroll
        for (int ks = 0; ks < 4; ks++) {
            uint32_t off = SWZ(base + (uint32_t)ks * 32);
            uint32_t bh0, bh1, bl0, bl1;
            ldmatrix_x2(bh0, bh1, sbGhi + off);
            ldmatrix_x2(bl0, bl1, sbGlo + off);
            mma_bf16(a0, a1, a2, a3, Ahi[ks], bh0, bh1);
            mma_bf16(a0, a1, a2, a3, Alo[ks], bh0, bh1);
            mma_bf16(a0, a1, a2, a3, Ahi[ks], bl0, bl1);
        }
        float2 wv = *(const float2*)&sww[n8 * 8 + tig * 2];
        z0 += wv.x * rcpf(1.f + __expf(-a0)) + wv.y * rcpf(1.f + __expf(-a1));
        z1 += wv.x * rcpf(1.f + __expf(-a2)) + wv.y * rcpf(1.f + __expf(-a3));
    }
    // reduce over the 4 threads sharing each row (tig)
    z0 += __shfl_xor_sync(0xffffffffu, z0, 1);
    z0 += __shfl_xor_sync(0xffffffffu, z0, 2);
    z1 += __shfl_xor_sync(0xffffffffu, z1, 1);
    z1 += __shfl_xor_sync(0xffffffffu, z1, 2);
    if (tig == 0) {
        g_zp[nch * 32768 + mrow0 + w * 16 + gid] = z0;
        g_zp[nch * 32768 + mrow0 + w * 16 + gid + 8] = z1;
    }
}

// zred: deterministic 11-way partial sum + outb + PReLU
__global__ __launch_bounds__(256) void k_zred(const float* __restrict__ outb,
                                              const float* __restrict__ pa,
                                              float* __restrict__ out) {
    int i = blockIdx.x * 256 + threadIdx.x;   // 32768
    float s = 0.f;
#pragma unroll
    for (int z = 0; z < 11; z++) s += g_zp[z * 32768 + i];
    s += outb[0];
    float a = pa[0];
    out[i] = s >= 0.f ? s : a * s;
}

extern "C" void kernel_launch(void* const* d_in, const int* in_sizes, int n_in,
                              void* d_out, int out_size) {
    const float* x   = (const float*)d_in[0];
    const float* fiW = (const float*)d_in[1];
    const float* fib = (const float*)d_in[2];
    const float* f1W = (const float*)d_in[3];
    const float* f1b = (const float*)d_in[4];
    const float* o1W = (const float*)d_in[5];
    const float* o1b = (const float*)d_in[6];
    const float* cnW = (const float*)d_in[7];
    const float* cnb = (const float*)d_in[8];
    const float* caW = (const float*)d_in[9];
    const float* oaW = (const float*)d_in[10];
    const float* ntW = (const float*)d_in[11];
    const float* gW  = (const float*)d_in[12];
    const float* omW = (const float*)d_in[13];
    const float* omb = (const float*)d_in[14];
    const float* pa  = (const float*)d_in[15];
    const float* cm  = (const float*)d_in[16];
    float* out = (float*)d_out;

    cudaFuncSetAttribute(k_ftc, cudaFuncAttributeMaxDynamicSharedMemorySize, 82048);

    fat1<<<1424, 256, 33792>>>(x, fiW, cm, cnW, cnb, caW, gW);
    fat2<<<2112, 256>>>(fib);
    fat3<<<384, 256, 17408>>>(f1W, oaW);
    fat4<<<768, 256>>>(ntW, f1b);
    fat5<<<1040, 256, 17408>>>(gW, o1W, o1b);
    fat6<<<784, 256, 34816>>>(ntW);
    k_ftc<<<2816, 256, 82048>>>(omW);
    k_zred<<<128, 256>>>(omb, pa, out);
}